// round 17
// baseline (speedup 1.0000x reference)
#include <cuda_runtime.h>
#include <cuda_fp16.h>
#include <math.h>
#include <stdint.h>

// Problem constants
#define DIMC   128
#define NWIN   49
#define HEADS  4
#define HD     32
#define NB     4096
#define M_TOTAL (NB * NWIN)        // 200704 = 1568 * 128
#define M_TILES (M_TOTAL / 128)    // 1568

// Scratch (allocation-free rule: static device globals)
__device__ __half g_qkv_h[(size_t)NB * NWIN * 384]; // [M, 384] fp16 q|k|v
__device__ __half g_projw_h[DIMC * DIMC];           // fp16 proj_w
__device__ float  g_comb[4 * 64 * 49 * 56];         // (bias+mask)*sqrt(hd)

__device__ __forceinline__ void mma_f16(float c[4], const uint32_t a[4],
                                        uint32_t b0, uint32_t b1) {
    asm volatile(
        "mma.sync.aligned.m16n8k16.row.col.f32.f16.f16.f32 "
        "{%0,%1,%2,%3}, {%4,%5,%6,%7}, {%8,%9}, {%0,%1,%2,%3};"
        : "+f"(c[0]), "+f"(c[1]), "+f"(c[2]), "+f"(c[3])
        : "r"(a[0]), "r"(a[1]), "r"(a[2]), "r"(a[3]), "r"(b0), "r"(b1));
}

__device__ __forceinline__ uint32_t packh2(float2 f) {
    __half2 h = __floats2half2_rn(f.x, f.y);   // low = f.x (k even), high = f.y
    return *(uint32_t*)&h;
}

#define CP_ASYNC16(dst, src) \
    asm volatile("cp.async.ca.shared.global [%0], [%1], 16;" :: "r"(dst), "l"(src))
#define CP_COMMIT() asm volatile("cp.async.commit_group;")

// ---------------------------------------------------------------------------
// GEMM1 v7 (frozen round-15/16 winner): fp16 tensor cores with
// convert-at-fragment-load. C[M][384] = A[M][128]*W[384][128]^T + bias (fp16).
// ---------------------------------------------------------------------------
#define G1_ROWF   24
#define G1_BUFB   (128 * G1_ROWF * 4)            // 12288 B per array buf
#define GEMM_SMEM_BYTES (6 * G1_BUFB)            // 73728

__device__ __forceinline__ void gemm_f16cvt_body(
    const float* __restrict__ A, const float* __restrict__ W,
    const float* __restrict__ bias, __half* __restrict__ C,
    float* sm, long m0, int n0)
{
    const int tid  = threadIdx.x;
    const int lane = tid & 31;
    const int warp = tid >> 5;
    const int wm   = warp & 1;
    const int wn   = warp >> 1;
    const int g    = lane >> 2;
    const int t    = lane & 3;

    const int srow = tid >> 2;
    const int sf   = tid & 3;
    const float* gA = A + (m0 + srow) * 128 + sf * 4;
    const float* gW = W + ((size_t)n0 + srow) * 128 + sf * 4;
    const uint32_t sbase = (uint32_t)__cvta_generic_to_shared(sm);
    const uint32_t sA = sbase + (srow * G1_ROWF + sf * 4) * 4;
    const uint32_t sW = sA + 3 * G1_BUFB;
    const uint32_t ROW64 = 64 * G1_ROWF * 4;

    auto stage = [&](int kc, int buf) {
        const float* a = gA + kc * 16;
        const float* w = gW + kc * 16;
        CP_ASYNC16(sA + buf * G1_BUFB,         a);
        CP_ASYNC16(sA + buf * G1_BUFB + ROW64, a + 64 * 128);
        CP_ASYNC16(sW + buf * G1_BUFB,         w);
        CP_ASYNC16(sW + buf * G1_BUFB + ROW64, w + 64 * 128);
    };

    float acc[4][4][4] = {};

    stage(0, 0); CP_COMMIT();
    stage(1, 1); CP_COMMIT();

    #pragma unroll
    for (int kc = 0; kc < 8; kc++) {
        if (kc < 7) asm volatile("cp.async.wait_group 1;");
        else        asm volatile("cp.async.wait_group 0;");
        __syncthreads();
        if (kc < 6) { stage(kc + 2, (kc + 2) % 3); CP_COMMIT(); }

        const float* Ab = sm + (kc % 3) * (128 * G1_ROWF);
        const float* Wb = Ab + 3 * (128 * G1_ROWF);

        uint32_t a[4][4];
        #pragma unroll
        for (int mt = 0; mt < 4; mt++) {
            const int r = wm * 64 + mt * 16 + g;
            a[mt][0] = packh2(*(const float2*)&Ab[r * G1_ROWF + 2 * t]);
            a[mt][1] = packh2(*(const float2*)&Ab[(r + 8) * G1_ROWF + 2 * t]);
            a[mt][2] = packh2(*(const float2*)&Ab[r * G1_ROWF + 8 + 2 * t]);
            a[mt][3] = packh2(*(const float2*)&Ab[(r + 8) * G1_ROWF + 8 + 2 * t]);
        }
        #pragma unroll
        for (int nt = 0; nt < 4; nt++) {
            const int n = wn * 32 + nt * 8 + g;
            uint32_t b0 = packh2(*(const float2*)&Wb[n * G1_ROWF + 2 * t]);
            uint32_t b1 = packh2(*(const float2*)&Wb[n * G1_ROWF + 8 + 2 * t]);
            #pragma unroll
            for (int mt = 0; mt < 4; mt++)
                mma_f16(acc[mt][nt], a[mt], b0, b1);
        }
    }

    #pragma unroll
    for (int nt = 0; nt < 4; nt++) {
        const int col = n0 + wn * 32 + nt * 8 + 2 * t;
        const float b0 = bias[col], b1 = bias[col + 1];
        #pragma unroll
        for (int mt = 0; mt < 4; mt++) {
            const long r = m0 + wm * 64 + mt * 16 + g;
            *(__half2*)&C[r * 384 + col] =
                __floats2half2_rn(acc[mt][nt][0] + b0, acc[mt][nt][1] + b1);
            *(__half2*)&C[(r + 8) * 384 + col] =
                __floats2half2_rn(acc[mt][nt][2] + b0, acc[mt][nt][3] + b1);
        }
    }
}

// GEMM1 (qkv, fp16) + fused precomp + proj_w fp16 conversion
__global__ __launch_bounds__(256, 2) void gemm1_precomp_kernel(
    const float* __restrict__ A, const float* __restrict__ W,
    const float* __restrict__ bias, __half* __restrict__ C,
    const float* __restrict__ mask, const float* __restrict__ bias_table,
    const int* __restrict__ rel_index, const float* __restrict__ proj_w)
{
    extern __shared__ float sm[];
    if (blockIdx.y >= M_TILES) {
        const int pid = (blockIdx.y - M_TILES) * 3 + blockIdx.x;
        if (pid < 256) {
            const int wm = pid & 63, h = pid >> 6;
            const float inv_scale = 5.656854249492381f;  // sqrt(32)
            float* dst = g_comb + ((size_t)h * 64 + wm) * 49 * 56;
            for (int q = threadIdx.x; q < 49 * 56; q += 256) {
                int i = q / 56, j = q - i * 56;
                dst[q] = (j < 49)
                    ? (bias_table[rel_index[i * 49 + j] * HEADS + h]
                       + mask[(size_t)wm * (NWIN * NWIN) + i * 49 + j]) * inv_scale
                    : -1e30f;
            }
        } else if (pid < 258) {
            const int base = (pid - 256) * 8192;
            for (int q = threadIdx.x; q < 8192; q += 256)
                g_projw_h[base + q] = __float2half(proj_w[base + q]);
        }
        return;
    }
    gemm_f16cvt_body(A, W, bias, C, sm, (long)blockIdx.y * 128, blockIdx.x * 128);
}

// ---------------------------------------------------------------------------
// Fused attention + projection. Block = window b, 256 thr = 8 warps.
// Attention: warp w -> head h = w>>1, half = w&1; owns rows half*32..+32
// (2 m16 tiles). One smem slab S[64][392] halfs: Q|K|V at cols 0|128|256
// (stride 196 words == 4 mod 32 -> conflict-free fragment LDS.32).
// P stays in registers (v6). O (fp16) overwrites the Q columns — safe:
// Q cols h*32 rows of a half are read only by the warp that writes them.
// Proj: 8 warps (2m x 4n), A-fragments from smem O, B-fragments LDG from
// g_projw_h (32 KB, L1-resident). Two block barriers total.
// ---------------------------------------------------------------------------
#define SLAB_W 392                                // halfs per row
#define AP_SMEM_BYTES (64 * SLAB_W * 2)           // 50176

__global__ __launch_bounds__(256, 2) void attn_proj_kernel(
    const __half* __restrict__ qkv, const __half* __restrict__ projw,
    const float* __restrict__ proj_b, float* __restrict__ outp)
{
    extern __shared__ __half S[];                 // [64][392]

    const int tid  = threadIdx.x;
    const int lane = tid & 31;
    const int warp = tid >> 5;
    const int g = lane >> 2, t = lane & 3;
    const int b = blockIdx.x;
    const int h    = warp >> 1;
    const int half = warp & 1;
    const float scale = 0.17677669529663687f;     // 32^-0.5

    // ---- stage qkv slab (49 rows x 384 halfs = 2352 x 16B lines) ----
    {
        const uint32_t sb = (uint32_t)__cvta_generic_to_shared(S);
        const __half* src = qkv + ((size_t)b * 49) * 384;
        for (int q = tid; q < 2352; q += 256) {
            const int i = q / 48, seg = q - i * 48;
            CP_ASYNC16(sb + i * (SLAB_W * 2) + seg * 16,
                       src + (size_t)i * 384 + seg * 8);
        }
        CP_COMMIT();
        // zero K pad rows 49..55 (cols 128..255) and V pad rows 49..63
        // (cols 256..383), as word stores
        uint32_t* Sw = (uint32_t*)S;
        for (int q = tid; q < 448; q += 256) {       // K: 7 rows x 64 words
            const int i = 49 + q / 64, w = q % 64;
            Sw[i * 196 + 64 + w] = 0u;
        }
        for (int q = tid; q < 960; q += 256) {       // V: 15 rows x 64 words
            const int i = 49 + q / 64, w = q % 64;
            Sw[i * 196 + 128 + w] = 0u;
        }
    }

    // ---- init S accumulators from comb*sqrt(hd) (overlaps with cp.async) ----
    const float* comb = g_comb + ((size_t)h * 64 + (b & 63)) * 49 * 56;
    float c[2][7][4];
    #pragma unroll
    for (int mt = 0; mt < 2; mt++) {
        const int rA = half * 32 + mt * 16 + g, rB = rA + 8;
        #pragma unroll
        for (int nt = 0; nt < 7; nt++) {
            const int col = nt * 8 + 2 * t;
            if (rA < 49) {
                float2 f = *(const float2*)&comb[rA * 56 + col];
                c[mt][nt][0] = f.x; c[mt][nt][1] = f.y;
            } else { c[mt][nt][0] = 0.f; c[mt][nt][1] = 0.f; }
            if (rB < 49) {
                float2 f = *(const float2*)&comb[rB * 56 + col];
                c[mt][nt][2] = f.x; c[mt][nt][3] = f.y;
            } else { c[mt][nt][2] = 0.f; c[mt][nt][3] = 0.f; }
        }
    }

    asm volatile("cp.async.wait_group 0;");
    __syncthreads();

    const uint32_t* Sw = (const uint32_t*)S;

    // ---- QK: S' = QK^T + comb*sqrt(hd)  (2 k-steps per m-tile) ----
    #pragma unroll
    for (int s = 0; s < 2; s++) {
        const int kw = s * 8 + t;                 // word offset within 32-half Q/K row
        uint32_t bfr[7][2];
        #pragma unroll
        for (int nt = 0; nt < 7; nt++) {
            const int n = nt * 8 + g;
            bfr[nt][0] = Sw[n * 196 + 64 + h * 16 + kw];
            bfr[nt][1] = Sw[n * 196 + 64 + h * 16 + kw + 4];
        }
        #pragma unroll
        for (int mt = 0; mt < 2; mt++) {
            const int rA = half * 32 + mt * 16 + g;
            uint32_t a[4];
            a[0] = Sw[rA * 196 + h * 16 + kw];
            a[1] = Sw[(rA + 8) * 196 + h * 16 + kw];
            a[2] = Sw[rA * 196 + h * 16 + kw + 4];
            a[3] = Sw[(rA + 8) * 196 + h * 16 + kw + 4];
            #pragma unroll
            for (int nt = 0; nt < 7; nt++)
                mma_f16(c[mt][nt], a, bfr[nt][0], bfr[nt][1]);
        }
    }

    // ---- softmax(scale * S') in registers; P stays in registers ----
    #pragma unroll
    for (int mt = 0; mt < 2; mt++) {
        float mx0 = -1e30f, mx1 = -1e30f;
        #pragma unroll
        for (int nt = 0; nt < 7; nt++) {
            mx0 = fmaxf(mx0, fmaxf(c[mt][nt][0], c[mt][nt][1]));
            mx1 = fmaxf(mx1, fmaxf(c[mt][nt][2], c[mt][nt][3]));
        }
        mx0 = fmaxf(mx0, __shfl_xor_sync(0xffffffffu, mx0, 1));
        mx0 = fmaxf(mx0, __shfl_xor_sync(0xffffffffu, mx0, 2));
        mx1 = fmaxf(mx1, __shfl_xor_sync(0xffffffffu, mx1, 1));
        mx1 = fmaxf(mx1, __shfl_xor_sync(0xffffffffu, mx1, 2));
        float s0 = 0.f, s1 = 0.f;
        #pragma unroll
        for (int nt = 0; nt < 7; nt++) {
            c[mt][nt][0] = __expf((c[mt][nt][0] - mx0) * scale);
            c[mt][nt][1] = __expf((c[mt][nt][1] - mx0) * scale);
            c[mt][nt][2] = __expf((c[mt][nt][2] - mx1) * scale);
            c[mt][nt][3] = __expf((c[mt][nt][3] - mx1) * scale);
            s0 += c[mt][nt][0] + c[mt][nt][1];
            s1 += c[mt][nt][2] + c[mt][nt][3];
        }
        s0 += __shfl_xor_sync(0xffffffffu, s0, 1);
        s0 += __shfl_xor_sync(0xffffffffu, s0, 2);
        s1 += __shfl_xor_sync(0xffffffffu, s1, 1);
        s1 += __shfl_xor_sync(0xffffffffu, s1, 2);
        const float i0 = 1.f / s0, i1 = 1.f / s1;
        #pragma unroll
        for (int nt = 0; nt < 7; nt++) {
            c[mt][nt][0] *= i0; c[mt][nt][1] *= i0;
            c[mt][nt][2] *= i1; c[mt][nt][3] *= i1;
        }
    }

    // ---- PV: O = P V (A-fragments packed straight from accumulators) ----
    float o[2][4][4] = {};
    #pragma unroll
    for (int s = 0; s < 4; s++) {
        const int k0 = s * 16;
        uint32_t bfr[4][2];
        #pragma unroll
        for (int nt = 0; nt < 4; nt++) {
            const int n = 256 + h * 32 + nt * 8 + g;
            bfr[nt][0] = (uint32_t)*(const unsigned short*)&S[(k0 + 2 * t) * SLAB_W + n]
                       | ((uint32_t)*(const unsigned short*)&S[(k0 + 2 * t + 1) * SLAB_W + n] << 16);
            bfr[nt][1] = (uint32_t)*(const unsigned short*)&S[(k0 + 8 + 2 * t) * SLAB_W + n]
                       | ((uint32_t)*(const unsigned short*)&S[(k0 + 9 + 2 * t) * SLAB_W + n] << 16);
        }
        #pragma unroll
        for (int mt = 0; mt < 2; mt++) {
            uint32_t a[4];
            a[0] = packh2(make_float2(c[mt][2 * s][0], c[mt][2 * s][1]));
            a[1] = packh2(make_float2(c[mt][2 * s][2], c[mt][2 * s][3]));
            if (2 * s + 1 < 7) {
                a[2] = packh2(make_float2(c[mt][2 * s + 1][0], c[mt][2 * s + 1][1]));
                a[3] = packh2(make_float2(c[mt][2 * s + 1][2], c[mt][2 * s + 1][3]));
            } else {
                a[2] = 0u; a[3] = 0u;
            }
            #pragma unroll
            for (int nt = 0; nt < 4; nt++)
                mma_f16(o[mt][nt], a, bfr[nt][0], bfr[nt][1]);
        }
    }

    // ---- write O (fp16) into the Q columns of the slab ----
    // Safe without a barrier: Q rows (half) x cols (h*32) are only read by
    // this warp's own QK A-fragments, which are complete.
    #pragma unroll
    for (int mt = 0; mt < 2; mt++) {
        const int rA = half * 32 + mt * 16 + g;
        #pragma unroll
        for (int nt = 0; nt < 4; nt++) {
            const int col = h * 32 + nt * 8 + 2 * t;
            *(__half2*)&S[rA * SLAB_W + col] =
                __floats2half2_rn(o[mt][nt][0], o[mt][nt][1]);
            *(__half2*)&S[(rA + 8) * SLAB_W + col] =
                __floats2half2_rn(o[mt][nt][2], o[mt][nt][3]);
        }
    }
    __syncthreads();

    // ---- proj: out = O @ proj_w^T + proj_b ----
    const int pm = warp & 1;           // 2 warps in m
    const int pn = warp >> 1;          // 4 warps in n
    float acc[2][4][4] = {};
    #pragma unroll
    for (int kc = 0; kc < 8; kc++) {
        const int kw = kc * 8 + t;     // word offset in the 128-half O row
        uint32_t bfr[4][2];
        #pragma unroll
        for (int nt = 0; nt < 4; nt++) {
            const int n = pn * 32 + nt * 8 + g;
            bfr[nt][0] = *(const uint32_t*)&projw[n * 128 + kc * 16 + 2 * t];
            bfr[nt][1] = *(const uint32_t*)&projw[n * 128 + kc * 16 + 8 + 2 * t];
        }
        #pragma unroll
        for (int mt = 0; mt < 2; mt++) {
            const int r = pm * 32 + mt * 16 + g;
            uint32_t a[4];
            a[0] = Sw[r * 196 + kw];
            a[1] = Sw[(r + 8) * 196 + kw];
            a[2] = Sw[r * 196 + kw + 4];
            a[3] = Sw[(r + 8) * 196 + kw + 4];
            #pragma unroll
            for (int nt = 0; nt < 4; nt++)
                mma_f16(acc[mt][nt], a, bfr[nt][0], bfr[nt][1]);
        }
    }

    #pragma unroll
    for (int nt = 0; nt < 4; nt++) {
        const int col = pn * 32 + nt * 8 + 2 * t;
        const float b0 = proj_b[col], b1 = proj_b[col + 1];
        #pragma unroll
        for (int mt = 0; mt < 2; mt++) {
            const int r = pm * 32 + mt * 16 + g;
            if (r < 49)
                *(float2*)&outp[((size_t)b * 49 + r) * DIMC + col]
                    = make_float2(acc[mt][nt][0] + b0, acc[mt][nt][1] + b1);
            if (r + 8 < 49)
                *(float2*)&outp[((size_t)b * 49 + r + 8) * DIMC + col]
                    = make_float2(acc[mt][nt][2] + b0, acc[mt][nt][3] + b1);
        }
    }
}

// ---------------------------------------------------------------------------
extern "C" void kernel_launch(void* const* d_in, const int* in_sizes, int n_in,
                              void* d_out, int out_size)
{
    const float* x          = (const float*)d_in[0];
    const float* mask       = (const float*)d_in[1];
    const float* qkv_w      = (const float*)d_in[2];
    const float* qkv_b      = (const float*)d_in[3];
    const float* proj_w     = (const float*)d_in[4];
    const float* proj_b     = (const float*)d_in[5];
    const float* bias_table = (const float*)d_in[6];
    const int*   rel_index  = (const int*)d_in[7];
    float*       out        = (float*)d_out;

    __half *qkvbuf = nullptr, *pwbuf = nullptr;
    cudaGetSymbolAddress((void**)&qkvbuf, g_qkv_h);
    cudaGetSymbolAddress((void**)&pwbuf, g_projw_h);

    cudaFuncSetAttribute(gemm1_precomp_kernel,
                         cudaFuncAttributeMaxDynamicSharedMemorySize, GEMM_SMEM_BYTES);
    cudaFuncSetAttribute(attn_proj_kernel,
                         cudaFuncAttributeMaxDynamicSharedMemorySize, AP_SMEM_BYTES);

    dim3 g1(384 / 128, M_TILES + 86);
    gemm1_precomp_kernel<<<g1, 256, GEMM_SMEM_BYTES>>>(
        x, qkv_w, qkv_b, qkvbuf, mask, bias_table, rel_index, proj_w);

    attn_proj_kernel<<<NB, 256, AP_SMEM_BYTES>>>(qkvbuf, pwbuf, proj_b, out);
}